// round 6
// baseline (speedup 1.0000x reference)
#include <cuda_runtime.h>
#include <cuda_bf16.h>
#include <cstdint>

#define BATCH 4
#define SEQ   4096
#define CDIM  512
#define DDIM  64
#define MROWS (BATCH*SEQ)
#define BKK   64
#define NT    (SEQ/BKK)

// device scratch (no allocation allowed)
__device__ __nv_bfloat16 g_xb [(size_t)MROWS * CDIM];         // bf16 x
__device__ __nv_bfloat16 g_wfT[DDIM * CDIM];                  // Wf^T [n][k]
__device__ __nv_bfloat16 g_wgT[DDIM * CDIM];                  // Wg^T
__device__ __nv_bfloat16 g_whT[CDIM * CDIM];                  // Wh^T
__device__ __nv_bfloat16 g_fb [MROWS * DDIM];                 // f  [m][64]
__device__ __nv_bfloat16 g_gb [MROWS * DDIM];                 // g  [m][64]
__device__ __nv_bfloat16 g_hTb[(size_t)BATCH * CDIM * SEQ];   // h^T [b][c][n]

typedef unsigned int u32;

__device__ __forceinline__ void cp16(void* dst, const void* src) {
    u32 s = (u32)__cvta_generic_to_shared(dst);
    asm volatile("cp.async.cg.shared.global [%0], [%1], 16;\n" :: "r"(s), "l"(src));
}
__device__ __forceinline__ void cp_commit() {
    asm volatile("cp.async.commit_group;\n");
}

__device__ __forceinline__ void mma16816(float* c, const u32* a, u32 b0, u32 b1) {
    asm volatile(
        "mma.sync.aligned.m16n8k16.row.col.f32.bf16.bf16.f32 "
        "{%0,%1,%2,%3}, {%4,%5,%6,%7}, {%8,%9}, {%0,%1,%2,%3};"
        : "+f"(c[0]), "+f"(c[1]), "+f"(c[2]), "+f"(c[3])
        : "r"(a[0]), "r"(a[1]), "r"(a[2]), "r"(a[3]), "r"(b0), "r"(b1));
}

// warp-collective: 4 x (8x8 b16) matrices; lane i supplies row (i&7) of matrix (i>>3)
__device__ __forceinline__ void ldsm4(u32* r, const void* p) {
    u32 a = (u32)__cvta_generic_to_shared(p);
    asm volatile("ldmatrix.sync.aligned.m8n8.x4.shared.b16 {%0,%1,%2,%3}, [%4];"
                 : "=r"(r[0]), "=r"(r[1]), "=r"(r[2]), "=r"(r[3]) : "r"(a));
}

// ---------------------------------------------------------------------------
// Cast kernels
// ---------------------------------------------------------------------------
__global__ void __launch_bounds__(256)
cast_x(const float* __restrict__ x, __nv_bfloat16* __restrict__ xb)
{
    const size_t i = (size_t)blockIdx.x * 256 + threadIdx.x;   // float4 index
    float4 v = ((const float4*)x)[i];
    __nv_bfloat162 a = __floats2bfloat162_rn(v.x, v.y);
    __nv_bfloat162 b = __floats2bfloat162_rn(v.z, v.w);
    *(__nv_bfloat162*)&xb[4 * i]     = a;
    *(__nv_bfloat162*)&xb[4 * i + 2] = b;
}

// W[K=512][N] fp32  ->  WT[N][512] bf16
__global__ void __launch_bounds__(256)
cast_wT(const float* __restrict__ W, __nv_bfloat16* __restrict__ WT, int N)
{
    const int i = blockIdx.x * 256 + threadIdx.x;
    if (i < N * CDIM) {
        int n = i >> 9, k = i & 511;
        WT[i] = __float2bfloat16(W[k * N + n]);
    }
}

// ---------------------------------------------------------------------------
// Tensor-core projections (round-5 structure, unchanged)
// ---------------------------------------------------------------------------
#define PSTR     72
#define P_OFF_A  0
#define P_A_T    18432
#define P_OFF_B  36864
#define P_B_T    9216
#define P_SMEM   55296

extern __shared__ __align__(16) unsigned char psm[];

__device__ __forceinline__ void proj_load_chunk(
    const __nv_bfloat16* A, const __nv_bfloat16* BT,
    int m0, int n0, int c, int buf, int t)
{
    __nv_bfloat16* sA = (__nv_bfloat16*)(psm + P_OFF_A + buf * P_A_T);
    __nv_bfloat16* sB = (__nv_bfloat16*)(psm + P_OFF_B + buf * P_B_T);
    #pragma unroll
    for (int r = 0; r < 4; r++) {
        int idx = t + 256 * r;
        int row = idx >> 3, ck = idx & 7;
        cp16(&sA[row * PSTR + ck * 8],
             A + (size_t)(m0 + row) * CDIM + c * 64 + ck * 8);
    }
    #pragma unroll
    for (int r = 0; r < 2; r++) {
        int idx = t + 256 * r;
        int row = idx >> 3, ck = idx & 7;
        cp16(&sB[row * PSTR + ck * 8],
             BT + (size_t)(n0 + row) * CDIM + c * 64 + ck * 8);
    }
    cp_commit();
}

__device__ __forceinline__ void proj_mainloop(
    const __nv_bfloat16* A, const __nv_bfloat16* BT,
    int m0, int n0, int t, int w, int gid, int tig, float o[8][4])
{
    #pragma unroll
    for (int nt = 0; nt < 8; nt++)
        #pragma unroll
        for (int j = 0; j < 4; j++) o[nt][j] = 0.f;

    proj_load_chunk(A, BT, m0, n0, 0, 0, t);
    proj_load_chunk(A, BT, m0, n0, 1, 1, t);

    const int lane = t & 31;
    for (int c = 0; c < 8; ++c) {
        if (c + 2 < 8) asm volatile("cp.async.wait_group 1;\n");
        else           asm volatile("cp.async.wait_group 0;\n");
        __syncthreads();
        const int buf = c & 1;
        const __nv_bfloat16* sA = (const __nv_bfloat16*)(psm + P_OFF_A + buf * P_A_T);
        const __nv_bfloat16* sB = (const __nv_bfloat16*)(psm + P_OFF_B + buf * P_B_T);

        u32 fa[4][4];
        const __nv_bfloat16* frow = &sA[(w * 16 + gid) * PSTR];
        #pragma unroll
        for (int ks = 0; ks < 4; ks++) {
            fa[ks][0] = *(const u32*)&frow[ks * 16 + 2 * tig];
            fa[ks][1] = *(const u32*)&frow[8 * PSTR + ks * 16 + 2 * tig];
            fa[ks][2] = *(const u32*)&frow[ks * 16 + 2 * tig + 8];
            fa[ks][3] = *(const u32*)&frow[8 * PSTR + ks * 16 + 2 * tig + 8];
        }
        #pragma unroll
        for (int nt = 0; nt < 8; nt++) {
            const __nv_bfloat16* bbase = &sB[(nt * 8 + (lane & 7)) * PSTR + (lane >> 3) * 8];
            u32 q0[4], q1[4];
            ldsm4(q0, bbase);
            ldsm4(q1, bbase + 32);
            mma16816(o[nt], fa[0], q0[0], q0[1]);
            mma16816(o[nt], fa[1], q0[2], q0[3]);
            mma16816(o[nt], fa[2], q1[0], q1[1]);
            mma16816(o[nt], fa[3], q1[2], q1[3]);
        }
        __syncthreads();
        if (c + 2 < 8) proj_load_chunk(A, BT, m0, n0, c + 2, buf, t);
        else           cp_commit();
    }
}

__global__ void __launch_bounds__(256)
proj_small(const __nv_bfloat16* __restrict__ A, const __nv_bfloat16* __restrict__ BT,
           const float* __restrict__ bias, __nv_bfloat16* __restrict__ out)
{
    const int m0 = blockIdx.x * 128;
    const int t = threadIdx.x, w = t >> 5, lane = t & 31;
    const int gid = lane >> 2, tig = lane & 3;

    float o[8][4];
    proj_mainloop(A, BT, m0, 0, t, w, gid, tig, o);

    const int r0 = m0 + w * 16 + gid;
    #pragma unroll
    for (int nt = 0; nt < 8; nt++) {
        const int cc = nt * 8 + 2 * tig;
        const float b0 = bias[cc], b1 = bias[cc + 1];
        __nv_bfloat162 v0 = __floats2bfloat162_rn(o[nt][0] + b0, o[nt][1] + b1);
        __nv_bfloat162 v1 = __floats2bfloat162_rn(o[nt][2] + b0, o[nt][3] + b1);
        *(__nv_bfloat162*)&out[(size_t)r0 * DDIM + cc]       = v0;
        *(__nv_bfloat162*)&out[(size_t)(r0 + 8) * DDIM + cc] = v1;
    }
}

#define TSTR 136
__global__ void __launch_bounds__(256)
proj_big(const __nv_bfloat16* __restrict__ A, const __nv_bfloat16* __restrict__ BT,
         const float* __restrict__ bias, __nv_bfloat16* __restrict__ outT)
{
    const int m0 = blockIdx.x * 128;
    const int n0 = blockIdx.y * 64;
    const int t = threadIdx.x, w = t >> 5, lane = t & 31;
    const int gid = lane >> 2, tig = lane & 3;

    float o[8][4];
    proj_mainloop(A, BT, m0, n0, t, w, gid, tig, o);

    __nv_bfloat16* st = (__nv_bfloat16*)psm;
    __syncthreads();
    const int m = w * 16 + gid;
    #pragma unroll
    for (int nt = 0; nt < 8; nt++) {
        const int cc = nt * 8 + 2 * tig;
        const float b0 = bias[n0 + cc], b1 = bias[n0 + cc + 1];
        st[cc * TSTR + m]           = __float2bfloat16(o[nt][0] + b0);
        st[(cc + 1) * TSTR + m]     = __float2bfloat16(o[nt][1] + b1);
        st[cc * TSTR + m + 8]       = __float2bfloat16(o[nt][2] + b0);
        st[(cc + 1) * TSTR + m + 8] = __float2bfloat16(o[nt][3] + b1);
    }
    __syncthreads();

    const int b  = m0 >> 12;
    const int nb = m0 & 4095;
    #pragma unroll
    for (int r = 0; r < 4; r++) {
        int idx = t + 256 * r;
        int row = idx >> 4, seg = idx & 15;
        float4 v = *(const float4*)&st[row * TSTR + seg * 8];
        *(float4*)&g_hTb[((size_t)b * CDIM + n0 + row) * SEQ + nb + seg * 8] = v;
    }
    (void)outT;
}

// ---------------------------------------------------------------------------
// mma.sync flash attention — round-4 structure + ldmatrix B-fragment loads
// ---------------------------------------------------------------------------
#define GSTR    72
#define OFF_F   0
#define OFF_G   18432
#define G_TILE  9216
#define OFF_H   36864
#define H_TILE  18432
#define SMEM_SZ 73728

extern __shared__ __align__(16) unsigned char smem_raw[];

__global__ void __launch_bounds__(256, 1)
attn_kernel(const float* __restrict__ x, const float* __restrict__ gamma_p,
            float* __restrict__ out)
{
    const int b   = blockIdx.y;
    const int q0  = blockIdx.x * 128;
    const int ch0 = blockIdx.z * 128;
    const int base = b * SEQ;
    const int t    = threadIdx.x;
    const int w    = t >> 5, lane = t & 31;
    const int gid  = lane >> 2, tig = lane & 3;
    const int lrow = lane & 7, lmat = lane >> 3;   // ldmatrix addressing

    __nv_bfloat16* sf = (__nv_bfloat16*)(smem_raw + OFF_F);
    __nv_bfloat16* sg = (__nv_bfloat16*)(smem_raw + OFF_G);
    __nv_bfloat16* sh = (__nv_bfloat16*)(smem_raw + OFF_H);

    const __nv_bfloat16* fptr = g_fb + (size_t)(base + q0) * DDIM;
    const __nv_bfloat16* gptr = g_gb + (size_t)base * DDIM;
    const __nv_bfloat16* hptr = g_hTb + ((size_t)b * CDIM + ch0) * SEQ;

    #pragma unroll
    for (int r = 0; r < 4; r++) {
        int idx = t + 256 * r;
        int row = idx >> 3, ck = idx & 7;
        cp16(&sf[row * GSTR + ck * 8], fptr + (size_t)row * DDIM + ck * 8);
    }
    #pragma unroll
    for (int r = 0; r < 2; r++) {
        int idx = t + 256 * r;
        int row = idx >> 3, ck = idx & 7;
        cp16(&sg[row * GSTR + ck * 8], gptr + (size_t)row * DDIM + ck * 8);
    }
    #pragma unroll
    for (int r = 0; r < 4; r++) {
        int idx = t + 256 * r;
        int row = idx >> 3, ck = idx & 7;
        cp16(&sh[row * GSTR + ck * 8], hptr + (size_t)row * SEQ + ck * 8);
    }
    cp_commit();
    {
        #pragma unroll
        for (int r = 0; r < 2; r++) {
            int idx = t + 256 * r;
            int row = idx >> 3, ck = idx & 7;
            cp16((unsigned char*)sg + G_TILE + (row * GSTR + ck * 8) * 2,
                 gptr + (size_t)(BKK + row) * DDIM + ck * 8);
        }
        #pragma unroll
        for (int r = 0; r < 4; r++) {
            int idx = t + 256 * r;
            int row = idx >> 3, ck = idx & 7;
            cp16((unsigned char*)sh + H_TILE + (row * GSTR + ck * 8) * 2,
                 hptr + (size_t)row * SEQ + BKK + ck * 8);
        }
    }
    cp_commit();
    asm volatile("cp.async.wait_group 1;\n");
    __syncthreads();

    u32 fa[4][4];
    {
        const __nv_bfloat16* frow = &sf[(w * 16 + gid) * GSTR];
        #pragma unroll
        for (int ks = 0; ks < 4; ks++) {
            fa[ks][0] = *(const u32*)&frow[ks * 16 + 2 * tig];
            fa[ks][1] = *(const u32*)&frow[8 * GSTR + ks * 16 + 2 * tig];
            fa[ks][2] = *(const u32*)&frow[ks * 16 + 2 * tig + 8];
            fa[ks][3] = *(const u32*)&frow[8 * GSTR + ks * 16 + 2 * tig + 8];
        }
    }

    float o[16][4];
    #pragma unroll
    for (int ct = 0; ct < 16; ct++)
        #pragma unroll
        for (int j = 0; j < 4; j++) o[ct][j] = 0.f;
    float l0 = 0.f, l1 = 0.f;

    for (int tt = 0; tt < NT; ++tt) {
        if (tt > 0) {
            if (tt + 1 < NT) asm volatile("cp.async.wait_group 1;\n");
            else             asm volatile("cp.async.wait_group 0;\n");
            __syncthreads();
        }
        const int buf = tt & 1;
        const __nv_bfloat16* gb = (const __nv_bfloat16*)((unsigned char*)sg + buf * G_TILE);
        const __nv_bfloat16* hb = (const __nv_bfloat16*)((unsigned char*)sh + buf * H_TILE);

        // ---- S = f . g^T : ldmatrix B-fragments (2 x4 per 8-key n-tile) ----
        float s[8][4];
        #pragma unroll
        for (int nt = 0; nt < 8; nt++)
            #pragma unroll
            for (int j = 0; j < 4; j++) s[nt][j] = 0.f;
        #pragma unroll
        for (int nt = 0; nt < 8; nt++) {
            const __nv_bfloat16* bbase = &gb[(nt * 8 + lrow) * GSTR + lmat * 8];
            u32 q0r[4], q1r[4];
            ldsm4(q0r, bbase);
            ldsm4(q1r, bbase + 32);
            mma16816(s[nt], fa[0], q0r[0], q0r[1]);
            mma16816(s[nt], fa[1], q0r[2], q0r[3]);
            mma16816(s[nt], fa[2], q1r[0], q1r[1]);
            mma16816(s[nt], fa[3], q1r[2], q1r[3]);
        }

        // ---- exp + pack P fragments (register-only) ----
        u32 pa[4][4];
        #pragma unroll
        for (int nt = 0; nt < 8; nt++) {
            float p0 = __expf(s[nt][0]);
            float p1 = __expf(s[nt][1]);
            float p2 = __expf(s[nt][2]);
            float p3 = __expf(s[nt][3]);
            l0 += p0 + p1;
            l1 += p2 + p3;
            __nv_bfloat162 lo = __floats2bfloat162_rn(p0, p1);
            __nv_bfloat162 hi = __floats2bfloat162_rn(p2, p3);
            pa[nt >> 1][(nt & 1) * 2 + 0] = *(u32*)&lo;
            pa[nt >> 1][(nt & 1) * 2 + 1] = *(u32*)&hi;
        }

        // ---- PV: O += P . h : ldmatrix B-fragments ----
        #pragma unroll
        for (int ct = 0; ct < 16; ct++) {
            const __nv_bfloat16* bbase = &hb[(ct * 8 + lrow) * GSTR + lmat * 8];
            u32 q0r[4], q1r[4];
            ldsm4(q0r, bbase);
            ldsm4(q1r, bbase + 32);
            mma16816(o[ct], pa[0], q0r[0], q0r[1]);
            mma16816(o[ct], pa[1], q0r[2], q0r[3]);
            mma16816(o[ct], pa[2], q1r[0], q1r[1]);
            mma16816(o[ct], pa[3], q1r[2], q1r[3]);
        }
        __syncthreads();

        if (tt + 2 < NT) {
            const int kt = (tt + 2) * BKK;
            #pragma unroll
            for (int r = 0; r < 2; r++) {
                int idx = t + 256 * r;
                int row = idx >> 3, ck = idx & 7;
                cp16((unsigned char*)sg + buf * G_TILE + (row * GSTR + ck * 8) * 2,
                     gptr + (size_t)(kt + row) * DDIM + ck * 8);
            }
            #pragma unroll
            for (int r = 0; r < 4; r++) {
                int idx = t + 256 * r;
                int row = idx >> 3, ck = idx & 7;
                cp16((unsigned char*)sh + buf * H_TILE + (row * GSTR + ck * 8) * 2,
                     hptr + (size_t)row * SEQ + kt + ck * 8);
            }
        }
        cp_commit();
    }

    l0 += __shfl_xor_sync(0xffffffffu, l0, 1);
    l0 += __shfl_xor_sync(0xffffffffu, l0, 2);
    l1 += __shfl_xor_sync(0xffffffffu, l1, 1);
    l1 += __shfl_xor_sync(0xffffffffu, l1, 2);
    const float gamma = *gamma_p;
    const float sc0 = gamma / l0;
    const float sc1 = gamma / l1;
    const size_t r0 = (size_t)(base + q0 + w * 16 + gid);
    const size_t r1 = r0 + 8;
    #pragma unroll
    for (int ct = 0; ct < 16; ct++) {
        const int c = ch0 + ct * 8 + 2 * tig;
        float2 x0 = *(const float2*)&x[r0 * CDIM + c];
        float2 x1 = *(const float2*)&x[r1 * CDIM + c];
        float2 o0, o1;
        o0.x = fmaf(o[ct][0], sc0, x0.x);
        o0.y = fmaf(o[ct][1], sc0, x0.y);
        o1.x = fmaf(o[ct][2], sc1, x1.x);
        o1.y = fmaf(o[ct][3], sc1, x1.y);
        *(float2*)&out[r0 * CDIM + c] = o0;
        *(float2*)&out[r1 * CDIM + c] = o1;
    }
}

// ---------------------------------------------------------------------------
extern "C" void kernel_launch(void* const* d_in, const int* in_sizes, int n_in,
                              void* d_out, int out_size)
{
    const float* x     = (const float*)d_in[0];
    const float* Wf    = (const float*)d_in[1];
    const float* bf    = (const float*)d_in[2];
    const float* Wg    = (const float*)d_in[3];
    const float* bg    = (const float*)d_in[4];
    const float* Wh    = (const float*)d_in[5];
    const float* bh    = (const float*)d_in[6];
    const float* gamma = (const float*)d_in[7];
    float* out = (float*)d_out;

    __nv_bfloat16 *xb, *wfT, *wgT, *whT, *fb, *gb, *hb;
    cudaGetSymbolAddress((void**)&xb,  g_xb);
    cudaGetSymbolAddress((void**)&wfT, g_wfT);
    cudaGetSymbolAddress((void**)&wgT, g_wgT);
    cudaGetSymbolAddress((void**)&whT, g_whT);
    cudaGetSymbolAddress((void**)&fb,  g_fb);
    cudaGetSymbolAddress((void**)&gb,  g_gb);
    cudaGetSymbolAddress((void**)&hb,  g_hTb);

    cast_x <<<MROWS * CDIM / 4 / 256, 256>>>(x, xb);
    cast_wT<<<CDIM * DDIM / 256, 256>>>(Wf, wfT, DDIM);
    cast_wT<<<CDIM * DDIM / 256, 256>>>(Wg, wgT, DDIM);
    cast_wT<<<CDIM * CDIM / 256, 256>>>(Wh, whT, CDIM);

    cudaFuncSetAttribute(proj_small,
                         cudaFuncAttributeMaxDynamicSharedMemorySize, P_SMEM);
    cudaFuncSetAttribute(proj_big,
                         cudaFuncAttributeMaxDynamicSharedMemorySize, P_SMEM);
    proj_small<<<dim3(MROWS / 128), 256, P_SMEM>>>(xb, wfT, bf, fb);
    proj_small<<<dim3(MROWS / 128), 256, P_SMEM>>>(xb, wgT, bg, gb);
    proj_big  <<<dim3(MROWS / 128, CDIM / 64), 256, P_SMEM>>>(xb, whT, bh, hb);

    cudaFuncSetAttribute(attn_kernel,
                         cudaFuncAttributeMaxDynamicSharedMemorySize, SMEM_SZ);
    attn_kernel<<<dim3(SEQ / 128, BATCH, CDIM / 128), 256, SMEM_SZ>>>(x, gamma, out);
}

// round 8
// speedup vs baseline: 1.0898x; 1.0898x over previous
#include <cuda_runtime.h>
#include <cuda_bf16.h>
#include <cstdint>

#define BATCH 4
#define SEQ   4096
#define CDIM  512
#define DDIM  64
#define MROWS (BATCH*SEQ)
#define NKB   32              // key blocks of 128 in skernel

// device scratch (no allocation allowed)
__device__ __nv_bfloat16 g_xb [(size_t)MROWS * CDIM];         // bf16 x
__device__ __nv_bfloat16 g_wfT[DDIM * CDIM];                  // Wf^T [n][k]
__device__ __nv_bfloat16 g_wgT[DDIM * CDIM];                  // Wg^T
__device__ __nv_bfloat16 g_whT[CDIM * CDIM];                  // Wh^T
__device__ __nv_bfloat16 g_fb [MROWS * DDIM];                 // f  [m][64]
__device__ __nv_bfloat16 g_gb [MROWS * DDIM];                 // g  [m][64]
__device__ __nv_bfloat16 g_hTb[(size_t)BATCH * CDIM * SEQ];   // h^T [b][c][n]
__device__ __nv_bfloat16 g_pb [(size_t)BATCH * SEQ * SEQ];    // P = exp(S) [b][q][k]  128 MB
__device__ float         g_lpart[NKB * MROWS];                // partial row sums
__device__ float         g_l[MROWS];                          // row sums

typedef unsigned int u32;

__device__ __forceinline__ void cp16(void* dst, const void* src) {
    u32 s = (u32)__cvta_generic_to_shared(dst);
    asm volatile("cp.async.cg.shared.global [%0], [%1], 16;\n" :: "r"(s), "l"(src));
}
__device__ __forceinline__ void cp_commit() {
    asm volatile("cp.async.commit_group;\n");
}

__device__ __forceinline__ void mma16816(float* c, const u32* a, u32 b0, u32 b1) {
    asm volatile(
        "mma.sync.aligned.m16n8k16.row.col.f32.bf16.bf16.f32 "
        "{%0,%1,%2,%3}, {%4,%5,%6,%7}, {%8,%9}, {%0,%1,%2,%3};"
        : "+f"(c[0]), "+f"(c[1]), "+f"(c[2]), "+f"(c[3])
        : "r"(a[0]), "r"(a[1]), "r"(a[2]), "r"(a[3]), "r"(b0), "r"(b1));
}

// ---------------------------------------------------------------------------
// Cast kernels
// ---------------------------------------------------------------------------
__global__ void __launch_bounds__(256)
cast_x(const float* __restrict__ x, __nv_bfloat16* __restrict__ xb)
{
    const size_t i = (size_t)blockIdx.x * 256 + threadIdx.x;
    float4 v = ((const float4*)x)[i];
    __nv_bfloat162 a = __floats2bfloat162_rn(v.x, v.y);
    __nv_bfloat162 b = __floats2bfloat162_rn(v.z, v.w);
    *(__nv_bfloat162*)&xb[4 * i]     = a;
    *(__nv_bfloat162*)&xb[4 * i + 2] = b;
}

__global__ void __launch_bounds__(256)
cast_wT(const float* __restrict__ W, __nv_bfloat16* __restrict__ WT, int N)
{
    const int i = blockIdx.x * 256 + threadIdx.x;
    if (i < N * CDIM) {
        int n = i >> 9, k = i & 511;
        WT[i] = __float2bfloat16(W[k * N + n]);
    }
}

// ---------------------------------------------------------------------------
// Generic bf16 GEMM mainloop: BM=128, BN=64, BK=64, 256 thr, double-buffered.
// A row-major [m][k], BT row-major [n][k]. o[8][4] per thread.
// ---------------------------------------------------------------------------
#define PSTR     72
#define P_OFF_A  0
#define P_A_T    18432
#define P_OFF_B  36864
#define P_B_T    9216
#define P_SMEM   55296

extern __shared__ __align__(16) unsigned char psm[];

__device__ __forceinline__ void load_chunk(
    const __nv_bfloat16* A, const __nv_bfloat16* BT,
    size_t strA, size_t strB, int m0, int n0, int c, int buf, int t)
{
    __nv_bfloat16* sA = (__nv_bfloat16*)(psm + P_OFF_A + buf * P_A_T);
    __nv_bfloat16* sB = (__nv_bfloat16*)(psm + P_OFF_B + buf * P_B_T);
    #pragma unroll
    for (int r = 0; r < 4; r++) {
        int idx = t + 256 * r;
        int row = idx >> 3, ck = idx & 7;
        cp16(&sA[row * PSTR + ck * 8],
             A + (size_t)(m0 + row) * strA + c * 64 + ck * 8);
    }
    #pragma unroll
    for (int r = 0; r < 2; r++) {
        int idx = t + 256 * r;
        int row = idx >> 3, ck = idx & 7;
        cp16(&sB[row * PSTR + ck * 8],
             BT + (size_t)(n0 + row) * strB + c * 64 + ck * 8);
    }
    cp_commit();
}

template <int NCHUNK>
__device__ __forceinline__ void gemm_mainloop(
    const __nv_bfloat16* A, const __nv_bfloat16* BT,
    size_t strA, size_t strB,
    int m0, int n0, int t, int w, int gid, int tig, float o[8][4])
{
    #pragma unroll
    for (int nt = 0; nt < 8; nt++)
        #pragma unroll
        for (int j = 0; j < 4; j++) o[nt][j] = 0.f;

    load_chunk(A, BT, strA, strB, m0, n0, 0, 0, t);
    load_chunk(A, BT, strA, strB, m0, n0, 1, 1, t);

    for (int c = 0; c < NCHUNK; ++c) {
        if (c + 2 < NCHUNK) asm volatile("cp.async.wait_group 1;\n");
        else                asm volatile("cp.async.wait_group 0;\n");
        __syncthreads();
        const int buf = c & 1;
        const __nv_bfloat16* sA = (const __nv_bfloat16*)(psm + P_OFF_A + buf * P_A_T);
        const __nv_bfloat16* sB = (const __nv_bfloat16*)(psm + P_OFF_B + buf * P_B_T);

        u32 fa[4][4];
        const __nv_bfloat16* frow = &sA[(w * 16 + gid) * PSTR];
        #pragma unroll
        for (int ks = 0; ks < 4; ks++) {
            fa[ks][0] = *(const u32*)&frow[ks * 16 + 2 * tig];
            fa[ks][1] = *(const u32*)&frow[8 * PSTR + ks * 16 + 2 * tig];
            fa[ks][2] = *(const u32*)&frow[ks * 16 + 2 * tig + 8];
            fa[ks][3] = *(const u32*)&frow[8 * PSTR + ks * 16 + 2 * tig + 8];
        }
        #pragma unroll
        for (int nt = 0; nt < 8; nt++) {
            const __nv_bfloat16* brow = &sB[(nt * 8 + gid) * PSTR + 2 * tig];
            #pragma unroll
            for (int ks = 0; ks < 4; ks++) {
                u32 b0 = *(const u32*)&brow[ks * 16];
                u32 b1 = *(const u32*)&brow[ks * 16 + 8];
                mma16816(o[nt], fa[ks], b0, b1);
            }
        }
        __syncthreads();
        if (c + 2 < NCHUNK) load_chunk(A, BT, strA, strB, m0, n0, c + 2, buf, t);
        else                cp_commit();
    }
}

// ---------------------------------------------------------------------------
// Projections
// ---------------------------------------------------------------------------
__global__ void __launch_bounds__(256)
proj_small(const __nv_bfloat16* __restrict__ A, const __nv_bfloat16* __restrict__ BT,
           const float* __restrict__ bias, __nv_bfloat16* __restrict__ out)
{
    const int m0 = blockIdx.x * 128;
    const int t = threadIdx.x, w = t >> 5, lane = t & 31;
    const int gid = lane >> 2, tig = lane & 3;

    float o[8][4];
    gemm_mainloop<8>(A, BT, CDIM, CDIM, m0, 0, t, w, gid, tig, o);

    const int r0 = m0 + w * 16 + gid;
    #pragma unroll
    for (int nt = 0; nt < 8; nt++) {
        const int cc = nt * 8 + 2 * tig;
        const float b0 = bias[cc], b1 = bias[cc + 1];
        __nv_bfloat162 v0 = __floats2bfloat162_rn(o[nt][0] + b0, o[nt][1] + b1);
        __nv_bfloat162 v1 = __floats2bfloat162_rn(o[nt][2] + b0, o[nt][3] + b1);
        *(__nv_bfloat162*)&out[(size_t)r0 * DDIM + cc]       = v0;
        *(__nv_bfloat162*)&out[(size_t)(r0 + 8) * DDIM + cc] = v1;
    }
}

#define TSTR 136
__global__ void __launch_bounds__(256)
proj_big(const __nv_bfloat16* __restrict__ A, const __nv_bfloat16* __restrict__ BT,
         const float* __restrict__ bias)
{
    const int m0 = blockIdx.x * 128;
    const int n0 = blockIdx.y * 64;
    const int t = threadIdx.x, w = t >> 5, lane = t & 31;
    const int gid = lane >> 2, tig = lane & 3;

    float o[8][4];
    gemm_mainloop<8>(A, BT, CDIM, CDIM, m0, n0, t, w, gid, tig, o);

    __nv_bfloat16* st = (__nv_bfloat16*)psm;
    __syncthreads();
    const int m = w * 16 + gid;
    #pragma unroll
    for (int nt = 0; nt < 8; nt++) {
        const int cc = nt * 8 + 2 * tig;
        const float b0 = bias[n0 + cc], b1 = bias[n0 + cc + 1];
        st[cc * TSTR + m]           = __float2bfloat16(o[nt][0] + b0);
        st[(cc + 1) * TSTR + m]     = __float2bfloat16(o[nt][1] + b1);
        st[cc * TSTR + m + 8]       = __float2bfloat16(o[nt][2] + b0);
        st[(cc + 1) * TSTR + m + 8] = __float2bfloat16(o[nt][3] + b1);
    }
    __syncthreads();

    const int b  = m0 >> 12;
    const int nb = m0 & 4095;
    #pragma unroll
    for (int r = 0; r < 4; r++) {
        int idx = t + 256 * r;
        int row = idx >> 4, seg = idx & 15;
        float4 v = *(const float4*)&st[row * TSTR + seg * 8];
        *(float4*)&g_hTb[((size_t)b * CDIM + n0 + row) * SEQ + nb + seg * 8] = v;
    }
}

// ---------------------------------------------------------------------------
// skernel: P[b][q][k] = exp(f_q . g_k), plus partial row sums.
// CTA: 128 q x 128 k, K=64 single chunk. Grid (32, 32, 4).
// ---------------------------------------------------------------------------
__global__ void __launch_bounds__(256)
skernel()
{
    __shared__ __nv_bfloat16 sf[128 * PSTR];
    __shared__ __nv_bfloat16 sg[128 * PSTR];

    const int qb = blockIdx.x, kb = blockIdx.y, b = blockIdx.z;
    const int q0 = qb * 128, k0 = kb * 128;
    const int t = threadIdx.x, w = t >> 5, lane = t & 31;
    const int gid = lane >> 2, tig = lane & 3;

    const __nv_bfloat16* fptr = g_fb + (size_t)(b * SEQ + q0) * DDIM;
    const __nv_bfloat16* gptr = g_gb + (size_t)(b * SEQ + k0) * DDIM;
    #pragma unroll
    for (int r = 0; r < 4; r++) {
        int idx = t + 256 * r;
        int row = idx >> 3, ck = idx & 7;
        cp16(&sf[row * PSTR + ck * 8], fptr + (size_t)row * DDIM + ck * 8);
    }
    #pragma unroll
    for (int r = 0; r < 4; r++) {
        int idx = t + 256 * r;
        int row = idx >> 3, ck = idx & 7;
        cp16(&sg[row * PSTR + ck * 8], gptr + (size_t)row * DDIM + ck * 8);
    }
    cp_commit();
    asm volatile("cp.async.wait_group 0;\n");
    __syncthreads();

    u32 fa[4][4];
    {
        const __nv_bfloat16* frow = &sf[(w * 16 + gid) * PSTR];
        #pragma unroll
        for (int ks = 0; ks < 4; ks++) {
            fa[ks][0] = *(const u32*)&frow[ks * 16 + 2 * tig];
            fa[ks][1] = *(const u32*)&frow[8 * PSTR + ks * 16 + 2 * tig];
            fa[ks][2] = *(const u32*)&frow[ks * 16 + 2 * tig + 8];
            fa[ks][3] = *(const u32*)&frow[8 * PSTR + ks * 16 + 2 * tig + 8];
        }
    }

    float s[16][4];
    #pragma unroll
    for (int nt = 0; nt < 16; nt++)
        #pragma unroll
        for (int j = 0; j < 4; j++) s[nt][j] = 0.f;

    #pragma unroll
    for (int nt = 0; nt < 16; nt++) {
        const __nv_bfloat16* brow = &sg[(nt * 8 + gid) * PSTR + 2 * tig];
        #pragma unroll
        for (int ks = 0; ks < 4; ks++) {
            u32 b0 = *(const u32*)&brow[ks * 16];
            u32 b1 = *(const u32*)&brow[ks * 16 + 8];
            mma16816(s[nt], fa[ks], b0, b1);
        }
    }

    // exp + store P + row partials
    __nv_bfloat16* P = g_pb + (size_t)b * SEQ * SEQ;
    const int row0 = q0 + w * 16 + gid;
    const int row1 = row0 + 8;
    float sl0 = 0.f, sl1 = 0.f;
    #pragma unroll
    for (int nt = 0; nt < 16; nt++) {
        float p0 = __expf(s[nt][0]);
        float p1 = __expf(s[nt][1]);
        float p2 = __expf(s[nt][2]);
        float p3 = __expf(s[nt][3]);
        sl0 += p0 + p1;
        sl1 += p2 + p3;
        const int key = k0 + nt * 8 + 2 * tig;
        __nv_bfloat162 lo = __floats2bfloat162_rn(p0, p1);
        __nv_bfloat162 hi = __floats2bfloat162_rn(p2, p3);
        *(__nv_bfloat162*)&P[(size_t)row0 * SEQ + key] = lo;
        *(__nv_bfloat162*)&P[(size_t)row1 * SEQ + key] = hi;
    }
    sl0 += __shfl_xor_sync(0xffffffffu, sl0, 1);
    sl0 += __shfl_xor_sync(0xffffffffu, sl0, 2);
    sl1 += __shfl_xor_sync(0xffffffffu, sl1, 1);
    sl1 += __shfl_xor_sync(0xffffffffu, sl1, 2);
    if (tig == 0) {
        g_lpart[kb * MROWS + b * SEQ + row0] = sl0;
        g_lpart[kb * MROWS + b * SEQ + row1] = sl1;
    }
}

__global__ void __launch_bounds__(256)
reduce_l()
{
    const int m = blockIdx.x * 256 + threadIdx.x;
    float s = 0.f;
    #pragma unroll
    for (int kb = 0; kb < NKB; kb++) s += g_lpart[kb * MROWS + m];
    g_l[m] = s;
}

// ---------------------------------------------------------------------------
// pvkernel: out = x + (gamma/l[row]) * (P . h^T). Pure GEMM + epilogue.
// Grid (8 ch-blocks, 128 m-blocks) — ch-major for P L2 reuse.
// ---------------------------------------------------------------------------
__global__ void __launch_bounds__(256)
pvkernel(const float* __restrict__ x, const float* __restrict__ gamma_p,
         float* __restrict__ out)
{
    const int n0 = blockIdx.x * 64;     // channel block
    const int m0 = blockIdx.y * 128;    // global row block (0..16383)
    const int b  = m0 >> 12;
    const int t = threadIdx.x, w = t >> 5, lane = t & 31;
    const int gid = lane >> 2, tig = lane & 3;

    const __nv_bfloat16* A  = g_pb + (size_t)b * SEQ * SEQ - (size_t)b * SEQ * SEQ
                            + (size_t)b * SEQ * SEQ;  // base for batch rows handled below
    // P rows are indexed globally: row m -> batch b=m>>12, q=m&4095
    // Since m0 block lies within one batch (128 | 4096), address directly:
    const __nv_bfloat16* Pq = g_pb + ((size_t)b * SEQ + (m0 & 4095)) * SEQ;
    const __nv_bfloat16* BT = g_hTb + (size_t)b * CDIM * SEQ;

    float o[8][4];
    gemm_mainloop<SEQ / 64>(Pq, BT, SEQ, SEQ, 0, n0, t, w, gid, tig, o);
    (void)A;

    const float gamma = *gamma_p;
    const int r0 = m0 + w * 16 + gid;
    const int r1 = r0 + 8;
    const float sc0 = gamma / g_l[r0];
    const float sc1 = gamma / g_l[r1];
    #pragma unroll
    for (int nt = 0; nt < 8; nt++) {
        const int cc = n0 + nt * 8 + 2 * tig;
        float2 x0 = *(const float2*)&x[(size_t)r0 * CDIM + cc];
        float2 x1 = *(const float2*)&x[(size_t)r1 * CDIM + cc];
        float2 o0, o1;
        o0.x = fmaf(o[nt][0], sc0, x0.x);
        o0.y = fmaf(o[nt][1], sc0, x0.y);
        o1.x = fmaf(o[nt][2], sc1, x1.x);
        o1.y = fmaf(o[nt][3], sc1, x1.y);
        *(float2*)&out[(size_t)r0 * CDIM + cc] = o0;
        *(float2*)&out[(size_t)r1 * CDIM + cc] = o1;
    }
}

// ---------------------------------------------------------------------------
extern "C" void kernel_launch(void* const* d_in, const int* in_sizes, int n_in,
                              void* d_out, int out_size)
{
    const float* x     = (const float*)d_in[0];
    const float* Wf    = (const float*)d_in[1];
    const float* bf    = (const float*)d_in[2];
    const float* Wg    = (const float*)d_in[3];
    const float* bg    = (const float*)d_in[4];
    const float* Wh    = (const float*)d_in[5];
    const float* bh    = (const float*)d_in[6];
    const float* gamma = (const float*)d_in[7];
    float* out = (float*)d_out;

    __nv_bfloat16 *xb, *wfT, *wgT, *whT, *fb, *gb;
    cudaGetSymbolAddress((void**)&xb,  g_xb);
    cudaGetSymbolAddress((void**)&wfT, g_wfT);
    cudaGetSymbolAddress((void**)&wgT, g_wgT);
    cudaGetSymbolAddress((void**)&whT, g_whT);
    cudaGetSymbolAddress((void**)&fb,  g_fb);
    cudaGetSymbolAddress((void**)&gb,  g_gb);

    cast_x <<<MROWS * CDIM / 4 / 256, 256>>>(x, xb);
    cast_wT<<<CDIM * DDIM / 256, 256>>>(Wf, wfT, DDIM);
    cast_wT<<<CDIM * DDIM / 256, 256>>>(Wg, wgT, DDIM);
    cast_wT<<<CDIM * CDIM / 256, 256>>>(Wh, whT, CDIM);

    cudaFuncSetAttribute(proj_small,
                         cudaFuncAttributeMaxDynamicSharedMemorySize, P_SMEM);
    cudaFuncSetAttribute(proj_big,
                         cudaFuncAttributeMaxDynamicSharedMemorySize, P_SMEM);
    cudaFuncSetAttribute(pvkernel,
                         cudaFuncAttributeMaxDynamicSharedMemorySize, P_SMEM);

    proj_small<<<dim3(MROWS / 128), 256, P_SMEM>>>(xb, wfT, bf, fb);
    proj_small<<<dim3(MROWS / 128), 256, P_SMEM>>>(xb, wgT, bg, gb);
    proj_big  <<<dim3(MROWS / 128, CDIM / 64), 256, P_SMEM>>>(xb, whT, bh);

    skernel <<<dim3(SEQ / 128, SEQ / 128, BATCH), 256>>>();
    reduce_l<<<MROWS / 256, 256>>>();

    pvkernel<<<dim3(CDIM / 64, MROWS / 128), 256, P_SMEM>>>(x, gamma, out);
}